// round 5
// baseline (speedup 1.0000x reference)
#include <cuda_runtime.h>
#include <cstdint>

// HashEmbedding: B*L=819200 tokens, H=2, E=64, out=[emb(64), pv0, pv1] f32
// d_in: words int32[819200], hash_table int32[1000000,2],
//       W f32[100000,64], P f32[1000000,2]

static constexpr int NTOK  = 16384 * 50;   // 819200
static constexpr int EMBED = 64;
static constexpr int OUTW  = EMBED + 2;    // 66
static constexpr int GRP   = 8;            // tokens per group
static constexpr int NGRP  = 2;            // groups per warp (software pipeline)
static constexpr int TPW   = GRP * NGRP;   // 16 tokens per warp
static constexpr int TPB   = 128;          // threads per block (reg granularity)

__global__ void __launch_bounds__(TPB)
hash_embedding_kernel(const int*    __restrict__ words,
                      const int2*   __restrict__ hash_table,
                      const float*  __restrict__ W,
                      const float2* __restrict__ P2,
                      float*        __restrict__ out)
{
    const int warp = (blockIdx.x * blockDim.x + threadIdx.x) >> 5;
    const int lane = threadIdx.x & 31;
    const int base = warp * TPW;
    if (base >= NTOK) return;
    const float* Pf = reinterpret_cast<const float*>(P2);

    // ---- Prologue: indices for group 0 ----
    int2 h_cur[GRP];
    {
        int w0[GRP];
#pragma unroll
        for (int t = 0; t < GRP; t++) w0[t] = __ldg(&words[base + t]);
#pragma unroll
        for (int t = 0; t < GRP; t++) h_cur[t] = __ldg(&hash_table[w0[t]]);
    }
    int w_cur[GRP];
#pragma unroll
    for (int t = 0; t < GRP; t++) w_cur[t] = __ldg(&words[base + t]); // rematerialize cheap (L1 hit)

#pragma unroll
    for (int g = 0; g < NGRP; g++) {
        const int gbase = base + g * GRP;

        // ---- Issue current group's data gathers (16 W rows + pw + pv) ----
        float2 a[GRP], b[GRP];
#pragma unroll
        for (int t = 0; t < GRP; t++) {
            a[t] = __ldg(reinterpret_cast<const float2*>(W + (size_t)h_cur[t].x * EMBED) + lane);
            b[t] = __ldg(reinterpret_cast<const float2*>(W + (size_t)h_cur[t].y * EMBED) + lane);
        }
        float2 pw[GRP];
#pragma unroll
        for (int t = 0; t < GRP; t++) pw[t] = __ldg(&P2[w_cur[t]]);

        float2 pv;
        if (lane < GRP) {
            pv.x = __ldg(&Pf[(size_t)h_cur[lane].x * 2 + 0]);
            pv.y = __ldg(&Pf[(size_t)h_cur[lane].y * 2 + 1]);
        }

        // ---- Prefetch next group's indices under the gather window ----
        int2 h_nxt[GRP];
        int  w_nxt[GRP];
        if (g + 1 < NGRP) {
            const int nbase = base + (g + 1) * GRP;
#pragma unroll
            for (int t = 0; t < GRP; t++) w_nxt[t] = __ldg(&words[nbase + t]);
#pragma unroll
            for (int t = 0; t < GRP; t++) h_nxt[t] = __ldg(&hash_table[w_nxt[t]]);
        }

        // ---- Consume + store current group ----
#pragma unroll
        for (int t = 0; t < GRP; t++) {
            float2 e;
            e.x = fmaf(a[t].x, pw[t].x, b[t].x * pw[t].y);
            e.y = fmaf(a[t].y, pw[t].x, b[t].y * pw[t].y);
            float* o = out + (size_t)(gbase + t) * OUTW;   // 264B stride, 8B aligned
            reinterpret_cast<float2*>(o)[lane] = e;        // cols 0..63
        }
        if (lane < GRP) {
            float* o = out + (size_t)(gbase + lane) * OUTW;
            *reinterpret_cast<float2*>(o + EMBED) = pv;    // cols 64..65
        }

        // rotate pipeline
#pragma unroll
        for (int t = 0; t < GRP; t++) { h_cur[t] = h_nxt[t]; w_cur[t] = w_nxt[t]; }
    }
}

extern "C" void kernel_launch(void* const* d_in, const int* in_sizes, int n_in,
                              void* d_out, int out_size)
{
    const int*    words      = (const int*)d_in[0];
    const int2*   hash_table = (const int2*)d_in[1];
    const float*  W          = (const float*)d_in[2];
    const float2* P          = (const float2*)d_in[3];
    float*        out        = (float*)d_out;

    const int tokens_per_block = (TPB / 32) * TPW;   // 64
    const int blocks = (NTOK + tokens_per_block - 1) / tokens_per_block;  // 12800
    hash_embedding_kernel<<<blocks, TPB>>>(words, hash_table, W, P, out);
}